// round 16
// baseline (speedup 1.0000x reference)
#include <cuda_runtime.h>
#include <math.h>

#define M_TOT 4507
#define CBK   71
#define POSTK 1000
#define HWT   53294      // 40000+10000+2500+625+169
#define NTOT  159882     // HWT*3

__device__ float g_wT[2304 * 256];
__device__ float g_h[2 * 256 * HWT];
__device__ float g_scores[2 * NTOT];
__device__ float g_deltas[2 * NTOT * 4];
__device__ float g_cboxes[2 * M_TOT * 4];
__device__ float g_cscores[2 * M_TOT];
__device__ float g_sboxes[2 * M_TOT * 4];
__device__ unsigned long long g_mask[2 * M_TOT * CBK];
__device__ int g_keeplist[2 * M_TOT];
__device__ int g_kcount[2];
__device__ unsigned g_hist16[10 * 65536];
__device__ unsigned long long g_cand[10 * 8192];
__device__ unsigned g_candcnt[10];
__device__ unsigned g_thrbin[10];

__device__ __forceinline__ unsigned ordf(float f) {
    unsigned u = __float_as_uint(f);
    return u ^ (((int)u < 0) ? 0xffffffffu : 0x80000000u);
}

// ---- transpose conv weights: cw[co][k] -> wT[k*256+co], k = ci*9+o (KCRS order)
__global__ void wtrans_kernel(const float* __restrict__ cw) {
    int idx = blockIdx.x * 256 + threadIdx.x;
    if (idx < 589824) {
        int k = idx >> 8, co = idx & 255;
        g_wT[idx] = cw[co * 2304 + k];
    }
}

// ---- clear per-(level,batch) histograms + counters ----
__global__ void clear_hist(int part) {
    int i = part * 327680 + blockIdx.x * 1024 + threadIdx.x;
    if (i < 655360) g_hist16[i] = 0u;
    if (part == 0 && i < 10) g_candcnt[i] = 0u;
}

// ---- big conv (P2/P3): 128-thread CTAs, 64 couts x 64 px, CPT=8, 4 px/thread.
// ---- 4-5 CTAs/SM -> staggered barriers/prefetch. Cout-pair f32x2 accumulation.
// ---- Exact KCRS k-order chain per scalar output (numerics-critical).
__global__ void __launch_bounds__(128, 4) conv3x3_big(
    const float* __restrict__ x, const float* __restrict__ bias,
    int H, int W, int HW, int lof)
{
    __shared__ float As[2][16][64];
    __shared__ float Bs[2][16][64];
    const int tid = threadIdx.x;
    const int tx = tid & 15, ty = tid >> 4;     // compute: tx->4 px, ty->8 couts
    const int lrow = tid >> 3;                  // loader: k-row 0..15
    const int lcol = (tid & 7) << 3;            // loader: col 0..56 step 8
    const int nb = blockIdx.x << 6;
    const int cb = blockIdx.y << 6;             // 64 couts per block
    const int b  = blockIdx.z;

    // loader pixel coords (8 pixels nb+lcol+j)
    int py[8], pxl[8]; bool pin[8];
#pragma unroll
    for (int j = 0; j < 8; ++j) {
        int ng = nb + lcol + j;
        pin[j] = ng < HW;
        int n2 = pin[j] ? ng : 0;
        py[j] = n2 / W; pxl[j] = n2 - py[j] * W;
    }
    const float* xb = x + (size_t)b * 256 * HW;

    unsigned long long acc[4][4];   // [cout-pair][pixel]
#pragma unroll
    for (int cp = 0; cp < 4; ++cp)
#pragma unroll
        for (int e = 0; e < 4; ++e) acc[cp][e] = 0ull;

    float4 av[2]; float bv[8];
    {
        const int k  = lrow;
        const int ci = k / 9;
        const int o  = k - ci * 9;
        const int ot = o / 3;
        const int dy = ot - 1;
        const int dx = o - ot * 3 - 1;
        av[0] = *(const float4*)&g_wT[(k << 8) + cb + lcol];
        av[1] = *(const float4*)&g_wT[(k << 8) + cb + lcol + 4];
        const float* xc = xb + (size_t)ci * HW;
#pragma unroll
        for (int j = 0; j < 8; ++j) {
            int hh = py[j] + dy, ww = pxl[j] + dx;
            bool ok = pin[j] && (unsigned)hh < (unsigned)H && (unsigned)ww < (unsigned)W;
            bv[j] = ok ? xc[hh * W + ww] : 0.f;
        }
    }

    for (int kt = 0; kt < 144; ++kt) {
        const int cur = kt & 1;
        *(float4*)&As[cur][lrow][lcol]     = av[0];
        *(float4*)&As[cur][lrow][lcol + 4] = av[1];
        *(float4*)&Bs[cur][lrow][lcol]     = make_float4(bv[0], bv[1], bv[2], bv[3]);
        *(float4*)&Bs[cur][lrow][lcol + 4] = make_float4(bv[4], bv[5], bv[6], bv[7]);
        __syncthreads();
        if (kt < 143) {
            const int k  = ((kt + 1) << 4) + lrow;
            const int ci = k / 9;
            const int o  = k - ci * 9;
            const int ot = o / 3;
            const int dy = ot - 1;
            const int dx = o - ot * 3 - 1;
            av[0] = *(const float4*)&g_wT[(k << 8) + cb + lcol];
            av[1] = *(const float4*)&g_wT[(k << 8) + cb + lcol + 4];
            const float* xc = xb + (size_t)ci * HW;
#pragma unroll
            for (int j = 0; j < 8; ++j) {
                int hh = py[j] + dy, ww = pxl[j] + dx;
                bool ok = pin[j] && (unsigned)hh < (unsigned)H && (unsigned)ww < (unsigned)W;
                bv[j] = ok ? xc[hh * W + ww] : 0.f;
            }
        }
#pragma unroll
        for (int kk = 0; kk < 16; ++kk) {
            ulonglong2 a01 = *(const ulonglong2*)&As[cur][kk][ty << 3];
            ulonglong2 a23 = *(const ulonglong2*)&As[cur][kk][(ty << 3) + 4];
            unsigned long long A2[4] = {a01.x, a01.y, a23.x, a23.y};
            float4 bq = *(const float4*)&Bs[cur][kk][tx << 2];
            unsigned long long B2[4];
            asm("mov.b64 %0, {%1,%1};" : "=l"(B2[0]) : "f"(bq.x));
            asm("mov.b64 %0, {%1,%1};" : "=l"(B2[1]) : "f"(bq.y));
            asm("mov.b64 %0, {%1,%1};" : "=l"(B2[2]) : "f"(bq.z));
            asm("mov.b64 %0, {%1,%1};" : "=l"(B2[3]) : "f"(bq.w));
#pragma unroll
            for (int cp = 0; cp < 4; ++cp)
#pragma unroll
                for (int e = 0; e < 4; ++e)
                    asm("fma.rn.f32x2 %0, %1, %2, %0;" : "+l"(acc[cp][e]) : "l"(A2[cp]), "l"(B2[e]));
        }
    }
#pragma unroll
    for (int cp = 0; cp < 4; ++cp) {
        int co0 = cb + (ty << 3) + (cp << 1);
        float bb0 = bias[co0], bb1 = bias[co0 + 1];
        float* op0 = g_h + ((size_t)b * 256 + co0) * HWT + lof;
        float* op1 = op0 + HWT;
#pragma unroll
        for (int e = 0; e < 4; ++e) {
            int ng = nb + (tx << 2) + e;
            if (ng < HW) {
                unsigned u0, u1;
                asm("mov.b64 {%0,%1}, %2;" : "=r"(u0), "=r"(u1) : "l"(acc[cp][e]));
                float t0 = __uint_as_float(u0) + bb0;
                float t1 = __uint_as_float(u1) + bb1;
                op0[ng] = t0 > 0.f ? t0 : 0.f;
                op1[ng] = t1 > 0.f ? t1 : 0.f;
            }
        }
    }
}

// ---- fused small-level conv (P4,P5,P6) in ONE launch (R15 proven) ----
__global__ void __launch_bounds__(256, 2) conv3x3_small(
    const float* __restrict__ x4, const float* __restrict__ x5,
    const float* __restrict__ x6, const float* __restrict__ bias)
{
    __shared__ float As[2][16][64];
    __shared__ float Bs[2][16][64];
    const int bx = blockIdx.x;
    int li, base;
    if (bx < 40) { li = 0; base = 0; }
    else if (bx < 50) { li = 1; base = 40; }
    else { li = 2; base = 50; }
    const int HWa[3] = {2500, 625, 169};
    const int Wa[3]  = {50, 25, 13};
    const int lofa[3] = {50000, 52500, 53125};
    const int HW = HWa[li], W = Wa[li], lof = lofa[li];
    const float* x = (li == 0) ? x4 : (li == 1) ? x5 : x6;

    const int tid = threadIdx.x;
    const int tx = tid & 15, ty = tid >> 4;
    const int nb = (bx - base) << 6;
    const int cb = blockIdx.y << 6;
    const int b  = blockIdx.z;

    int py[4], px[4]; bool pin[4];
#pragma unroll
    for (int e = 0; e < 4; ++e) {
        int ng = nb + (tx << 2) + e;
        pin[e] = ng < HW;
        int ngc = pin[e] ? ng : 0;
        py[e] = ngc / W;
        px[e] = ngc - py[e] * W;
    }
    const float* xb = x + (size_t)b * 256 * HW;

    unsigned long long acc[2][4];
#pragma unroll
    for (int cp = 0; cp < 2; ++cp)
#pragma unroll
        for (int e = 0; e < 4; ++e) acc[cp][e] = 0ull;

    float4 av; float bv[4];
    {
        const int k  = ty;
        const int ci = k / 9;
        const int o  = k - ci * 9;
        const int ot = o / 3;
        const int dy = ot - 1;
        const int dx = o - ot * 3 - 1;
        av = *(const float4*)&g_wT[(k << 8) + cb + (tx << 2)];
        const float* xc = xb + (size_t)ci * HW;
#pragma unroll
        for (int e = 0; e < 4; ++e) {
            int hh = py[e] + dy, ww = px[e] + dx;
            bool ok = pin[e] && (unsigned)hh < (unsigned)W && (unsigned)ww < (unsigned)W;
            bv[e] = ok ? xc[hh * W + ww] : 0.f;
        }
    }

    for (int kt = 0; kt < 144; ++kt) {
        const int cur = kt & 1;
        *(float4*)&As[cur][ty][tx << 2] = av;
        *(float4*)&Bs[cur][ty][tx << 2] = make_float4(bv[0], bv[1], bv[2], bv[3]);
        __syncthreads();
        if (kt < 143) {
            const int k  = ((kt + 1) << 4) + ty;
            const int ci = k / 9;
            const int o  = k - ci * 9;
            const int ot = o / 3;
            const int dy = ot - 1;
            const int dx = o - ot * 3 - 1;
            av = *(const float4*)&g_wT[(k << 8) + cb + (tx << 2)];
            const float* xc = xb + (size_t)ci * HW;
#pragma unroll
            for (int e = 0; e < 4; ++e) {
                int hh = py[e] + dy, ww = px[e] + dx;
                bool ok = pin[e] && (unsigned)hh < (unsigned)W && (unsigned)ww < (unsigned)W;
                bv[e] = ok ? xc[hh * W + ww] : 0.f;
            }
        }
#pragma unroll
        for (int kk = 0; kk < 16; ++kk) {
            ulonglong2 aq = *(const ulonglong2*)&As[cur][kk][ty << 2];
            unsigned long long A2[2] = {aq.x, aq.y};
            float4 bq = *(const float4*)&Bs[cur][kk][tx << 2];
            unsigned long long B2[4];
            asm("mov.b64 %0, {%1,%1};" : "=l"(B2[0]) : "f"(bq.x));
            asm("mov.b64 %0, {%1,%1};" : "=l"(B2[1]) : "f"(bq.y));
            asm("mov.b64 %0, {%1,%1};" : "=l"(B2[2]) : "f"(bq.z));
            asm("mov.b64 %0, {%1,%1};" : "=l"(B2[3]) : "f"(bq.w));
#pragma unroll
            for (int cp = 0; cp < 2; ++cp)
#pragma unroll
                for (int e = 0; e < 4; ++e)
                    asm("fma.rn.f32x2 %0, %1, %2, %0;" : "+l"(acc[cp][e]) : "l"(A2[cp]), "l"(B2[e]));
        }
    }
#pragma unroll
    for (int cp = 0; cp < 2; ++cp) {
        int co0 = cb + (ty << 2) + (cp << 1);
        float bb0 = bias[co0], bb1 = bias[co0 + 1];
        float* op0 = g_h + ((size_t)b * 256 + co0) * HWT + lof;
        float* op1 = op0 + HWT;
#pragma unroll
        for (int e = 0; e < 4; ++e) {
            int ng = nb + (tx << 2) + e;
            if (ng < HW) {
                unsigned u0, u1;
                asm("mov.b64 {%0,%1}, %2;" : "=r"(u0), "=r"(u1) : "l"(acc[cp][e]));
                float t0 = __uint_as_float(u0) + bb0;
                float t1 = __uint_as_float(u1) + bb1;
                op0[ng] = t0 > 0.f ? t0 : 0.f;
                op1[ng] = t1 > 0.f ? t1 : 0.f;
            }
        }
    }
}

// ---- fused 1x1 heads over ALL levels in one launch ----
__global__ void heads_kernel(const float* __restrict__ lw, const float* __restrict__ lb,
                             const float* __restrict__ dw, const float* __restrict__ db)
{
    __shared__ float ws[15 * 256];
    __shared__ float wb[15];
    const int tid = threadIdx.x;
    for (int i = tid; i < 768;  i += 128) ws[i] = lw[i];
    for (int i = tid; i < 3072; i += 128) ws[768 + i] = dw[i];
    if (tid < 3) wb[tid] = lb[tid];
    else if (tid < 15) wb[tid] = db[tid - 3];
    __syncthreads();
    const int b = blockIdx.y;
    const int p = blockIdx.x * 128 + tid;
    if (p >= HWT) return;
    const float* hb = g_h + (size_t)b * 256 * HWT + p;
    float acc[15];
#pragma unroll
    for (int o = 0; o < 15; ++o) acc[o] = 0.f;
    for (int c = 0; c < 256; ++c) {
        float v = hb[(size_t)c * HWT];
#pragma unroll
        for (int o = 0; o < 15; ++o) acc[o] = __fmaf_rn(ws[(o << 8) + c], v, acc[o]);
    }
    size_t base = (size_t)b * NTOT + (size_t)p * 3;
#pragma unroll
    for (int a = 0; a < 3; ++a) g_scores[base + a] = acc[a] + wb[a];
#pragma unroll
    for (int a = 0; a < 3; ++a)
#pragma unroll
        for (int j = 0; j < 4; ++j)
            g_deltas[(base + a) * 4 + j] = acc[3 + (a << 2) + j] + wb[3 + (a << 2) + j];
}

__constant__ int c_Ns[5]    = {120000, 30000, 7500, 1875, 507};
__constant__ int c_soff[5]  = {0, 120000, 150000, 157500, 159375};
__constant__ int c_Ks[5]    = {1000, 1000, 1000, 1000, 507};
__constant__ int c_offs[5]  = {0, 1000, 2000, 3000, 4000};

// ==== parallel exact top-K, all (level,batch) in single launches ====
__global__ void topk_hist() {
    int lb = blockIdx.y; int lvl = lb >> 1, b = lb & 1;
    int N = c_Ns[lvl];
    unsigned* hist = g_hist16 + lb * 65536;
    const float* sc = g_scores + (size_t)b * NTOT + c_soff[lvl];
    for (int i = blockIdx.x * 1024 + threadIdx.x; i < N; i += gridDim.x * 1024)
        atomicAdd(&hist[ordf(sc[i]) >> 16], 1u);
}

__global__ void topk_thresh() {
    int lb = blockIdx.x;
    int K = c_Ks[lb >> 1];
    int tid = threadIdx.x;
    __shared__ unsigned csum[1024];
    const unsigned* hist = g_hist16 + lb * 65536;
    unsigned s = 0;
    for (int j = 0; j < 64; ++j) s += hist[tid * 64 + j];
    csum[tid] = s;
    __syncthreads();
    if (tid == 0) {
        unsigned acc = 0; int c = 0;
        for (c = 1023; c >= 0; --c) {
            if (acc + csum[c] >= (unsigned)K) break;
            acc += csum[c];
        }
        unsigned thr = 0;
        for (int j = 63; j >= 0; --j) {
            unsigned h = hist[c * 64 + j];
            if (acc + h >= (unsigned)K) { thr = c * 64 + j; break; }
            acc += h;
        }
        g_thrbin[lb] = thr;
    }
}

__global__ void topk_gather() {
    int lb = blockIdx.y; int lvl = lb >> 1, b = lb & 1;
    int N = c_Ns[lvl];
    unsigned thr = g_thrbin[lb];
    const float* sc = g_scores + (size_t)b * NTOT + c_soff[lvl];
    for (int i = blockIdx.x * 1024 + threadIdx.x; i < N; i += gridDim.x * 1024) {
        unsigned o = ordf(sc[i]);
        if ((o >> 16) >= thr) {
            unsigned p = atomicAdd(&g_candcnt[lb], 1u);
            if (p < 8192)
                g_cand[lb * 8192 + p] = (((unsigned long long)o) << 32) | (unsigned)(~i);
        }
    }
}

__global__ void topk_final(const float* __restrict__ a0, const float* __restrict__ a1,
                           const float* __restrict__ a2, const float* __restrict__ a3,
                           const float* __restrict__ a4) {
    extern __shared__ unsigned long long sk2[];
    int lb = blockIdx.x; int lvl = lb >> 1, b = lb & 1;
    int tid = threadIdx.x;
    int K = c_Ks[lvl];
    const float* ancs[5] = {a0, a1, a2, a3, a4};
    const float* anchors = ancs[lvl];
    unsigned cnt = min(g_candcnt[lb], 8192u);
    int SZ = (cnt <= 2048u) ? 2048 : 8192;
    for (int i = tid; i < SZ; i += 1024)
        sk2[i] = (i < (int)cnt) ? g_cand[lb * 8192 + i] : 0ull;
    __syncthreads();
    for (unsigned k = 2; k <= (unsigned)SZ; k <<= 1) {
        for (unsigned j = k >> 1; j; j >>= 1) {
            for (unsigned e = tid; e < (unsigned)SZ; e += 1024) {
                unsigned ixj = e ^ j;
                if (ixj > e) {
                    unsigned long long a = sk2[e], c = sk2[ixj];
                    bool up = ((e & k) == 0);
                    if ((a < c) == up) { sk2[e] = c; sk2[ixj] = a; }  // descending
                }
            }
            __syncthreads();
        }
    }
    if (tid < K) {
        unsigned long long key = sk2[tid];
        unsigned idx = ~(unsigned)(key & 0xffffffffull);
        const float* sc = g_scores + (size_t)b * NTOT + c_soff[lvl];
        float s = sc[idx];
        const float* dl = g_deltas + ((size_t)b * NTOT + c_soff[lvl] + idx) * 4;
        float d0 = dl[0], d1 = dl[1], d2 = dl[2], d3 = dl[3];
        const float* an = anchors + (size_t)idx * 4;
        float aa0 = an[0], aa1 = an[1], aa2 = an[2], aa3 = an[3];
        float wa = __fsub_rn(aa2, aa0), ha = __fsub_rn(aa3, aa1);
        float xa = __fadd_rn(aa0, __fmul_rn(0.5f, wa));
        float ya = __fadd_rn(aa1, __fmul_rn(0.5f, ha));
        float cx = __fadd_rn(__fmul_rn(d0, wa), xa);
        float cy = __fadd_rn(__fmul_rn(d1, ha), ya);
        float w  = __fmul_rn(wa, expf(d2));
        float h  = __fmul_rn(ha, expf(d3));
        float x0 = __fsub_rn(cx, __fmul_rn(0.5f, w));
        float y0 = __fsub_rn(cy, __fmul_rn(0.5f, h));
        float x1 = __fadd_rn(cx, __fmul_rn(0.5f, w));
        float y1 = __fadd_rn(cy, __fmul_rn(0.5f, h));
        x0 = fminf(fmaxf(x0, 0.f), 800.f); y0 = fminf(fmaxf(y0, 0.f), 800.f);
        x1 = fminf(fmaxf(x1, 0.f), 800.f); y1 = fminf(fmaxf(y1, 0.f), 800.f);
        bool valid = (x1 > x0) && (y1 > y0);
        int ci = b * M_TOT + c_offs[lvl] + tid;
        g_cboxes[ci * 4 + 0] = x0; g_cboxes[ci * 4 + 1] = y0;
        g_cboxes[ci * 4 + 2] = x1; g_cboxes[ci * 4 + 3] = y1;
        g_cscores[ci] = valid ? s : -1000000000.0f;
    }
}

// ---- global stable sort by descending score (bitonic over 8192) + gather ----
__global__ void sort_kernel() {
    extern __shared__ unsigned long long sk[];
    int b = blockIdx.x, tid = threadIdx.x;
    for (int i = tid; i < 8192; i += 1024) {
        unsigned long long k = 0xFFFFFFFFFFFFFFFFull;
        if (i < M_TOT) {
            float s = g_cscores[b * M_TOT + i];
            k = (((unsigned long long)(~ordf(s))) << 32) | (unsigned)i;
        }
        sk[i] = k;
    }
    __syncthreads();
    for (unsigned kk = 2; kk <= 8192; kk <<= 1) {
        for (unsigned j = kk >> 1; j; j >>= 1) {
            for (unsigned e = tid; e < 8192; e += 1024) {
                unsigned ixj = e ^ j;
                if (ixj > e) {
                    unsigned long long a = sk[e], c = sk[ixj];
                    if (((e & kk) == 0) ? (a > c) : (a < c)) { sk[e] = c; sk[ixj] = a; }
                }
            }
            __syncthreads();
        }
    }
    for (int i = tid; i < M_TOT; i += 1024) {
        unsigned idx = (unsigned)(sk[i] & 0xffffffffull);
        float4 bx = *(float4*)&g_cboxes[(b * M_TOT + idx) * 4];
        *(float4*)&g_sboxes[(b * M_TOT + i) * 4] = bx;
    }
}

// ---- NMS suppression mask (64-bit blocks) ----
__global__ void nms_mask_kernel() {
    int b = blockIdx.z;
    int rb = blockIdx.x, cbi = blockIdx.y;
    __shared__ float4 cbox[64];
    int t = threadIdx.x;
    int col0 = cbi * 64;
    if (col0 + t < M_TOT) cbox[t] = *(float4*)&g_sboxes[(b * M_TOT + col0 + t) * 4];
    else cbox[t] = make_float4(0, 0, 0, 0);
    __syncthreads();
    int row = rb * 64 + t;
    if (row >= M_TOT) return;
    float4 rbx = *(float4*)&g_sboxes[(b * M_TOT + row) * 4];
    float rarea = __fmul_rn(__fsub_rn(rbx.z, rbx.x), __fsub_rn(rbx.w, rbx.y));
    unsigned long long bits = 0;
    int cmax = min(64, M_TOT - col0);
    for (int c = 0; c < cmax; ++c) {
        int col = col0 + c;
        if (col <= row) continue;
        float4 cb = cbox[c];
        float carea = __fmul_rn(__fsub_rn(cb.z, cb.x), __fsub_rn(cb.w, cb.y));
        float lx = fmaxf(rbx.x, cb.x), ly = fmaxf(rbx.y, cb.y);
        float rx = fminf(rbx.z, cb.z), ry = fminf(rbx.w, cb.w);
        float w = fmaxf(__fsub_rn(rx, lx), 0.f), h = fmaxf(__fsub_rn(ry, ly), 0.f);
        float inter = __fmul_rn(w, h);
        float den = __fadd_rn(__fsub_rn(__fadd_rn(rarea, carea), inter), 1e-9f);
        float iou = __fdiv_rn(inter, den);
        if (iou > 0.7f) bits |= 1ull << c;
    }
    g_mask[((size_t)b * M_TOT + row) * CBK + cbi] = bits;
}

// ---- sequential NMS reduce: one warp per batch, smem double-buffered chunks ----
#define NCHUNK 16
__global__ void nms_reduce_kernel() {
    __shared__ unsigned long long buf[2][NCHUNK * CBK];
    int b = blockIdx.x;
    int lane = threadIdx.x;
    const unsigned long long* mrow = g_mask + (size_t)b * M_TOT * CBK;
    unsigned long long rm0 = 0, rm1 = 0, rm2 = 0;
    int cnt = 0;
    const int nchunks = (M_TOT + NCHUNK - 1) / NCHUNK;
    for (int i = lane; i < NCHUNK * CBK; i += 32)
        buf[0][i] = mrow[i];
    __syncwarp();
    for (int c = 0; c < nchunks; ++c) {
        int cur = c & 1, nxt = cur ^ 1;
        if (c + 1 < nchunks) {
            size_t base = (size_t)(c + 1) * NCHUNK * CBK;
            for (int i = lane; i < NCHUNK * CBK; i += 32) {
                int rr = (c + 1) * NCHUNK + i / CBK;
                buf[nxt][i] = (rr < M_TOT) ? mrow[base + i] : 0ull;
            }
        }
        int rmax = min(NCHUNK, M_TOT - c * NCHUNK);
        for (int j = 0; j < rmax; ++j) {
            int r = c * NCHUNK + j;
            int wq = r >> 6; int slot = wq >> 5; int src = wq & 31;
            unsigned long long rv = (slot == 0) ? rm0 : ((slot == 1) ? rm1 : rm2);
            unsigned long long v = __shfl_sync(0xffffffffu, rv, src);
            bool keep = !((v >> (r & 63)) & 1ull);
            if (keep) {
                unsigned long long m0 = (lane      < CBK) ? buf[cur][j * CBK + lane]      : 0ull;
                unsigned long long m1 = (lane + 32 < CBK) ? buf[cur][j * CBK + lane + 32] : 0ull;
                unsigned long long m2 = (lane + 64 < CBK) ? buf[cur][j * CBK + lane + 64] : 0ull;
                rm0 |= m0; rm1 |= m1; rm2 |= m2;
                if (lane == 0) g_keeplist[b * M_TOT + cnt] = r;
                cnt++;
            }
        }
        __syncwarp();
    }
    if (lane == 0) g_kcount[b] = cnt;
}

// ---- emit final output ----
__global__ void emit_kernel(float* out) {
    int b = blockIdx.y;
    int j = blockIdx.x * 256 + threadIdx.x;
    if (j >= POSTK) return;
    int kc = g_kcount[b];
    float4 v = make_float4(0, 0, 0, 0);
    if (j < kc) {
        int r = g_keeplist[b * M_TOT + j];
        v = *(float4*)&g_sboxes[(b * M_TOT + r) * 4];
    }
    ((float4*)out)[b * POSTK + j] = v;
}

extern "C" void kernel_launch(void* const* d_in, const int* in_sizes, int n_in,
                              void* d_out, int out_size) {
    const float *feat[5] = {0}, *anc[5] = {0};
    const float *cw = 0, *cb = 0, *lw = 0, *lb = 0, *dw = 0, *db = 0;
    for (int i = 0; i < n_in; ++i) {
        const float* p = (const float*)d_in[i];
        switch (in_sizes[i]) {
            case 20480000: feat[0] = p; break;
            case 5120000:  feat[1] = p; break;
            case 1280000:  feat[2] = p; break;
            case 320000:   feat[3] = p; break;
            case 86528:    feat[4] = p; break;
            case 480000:   anc[0] = p; break;
            case 120000:   anc[1] = p; break;
            case 30000:    anc[2] = p; break;
            case 7500:     anc[3] = p; break;
            case 2028:     anc[4] = p; break;
            case 589824:   cw = p; break;
            case 256:      cb = p; break;
            case 768:      lw = p; break;
            case 3:        lb = p; break;
            case 3072:     dw = p; break;
            case 12:       db = p; break;
        }
    }

    cudaFuncSetAttribute(topk_final, cudaFuncAttributeMaxDynamicSharedMemorySize, 65536);
    cudaFuncSetAttribute(sort_kernel, cudaFuncAttributeMaxDynamicSharedMemorySize, 65536);

    // launches 1-3 (slot #4 = P2 conv for ncu)
    wtrans_kernel<<<2304, 256>>>(cw);
    clear_hist<<<320, 1024>>>(0);
    clear_hist<<<320, 1024>>>(1);

    // convs
    conv3x3_big<<<dim3(625, 4, 2), 128>>>(feat[0], cb, 200, 200, 40000, 0);
    conv3x3_big<<<dim3(157, 4, 2), 128>>>(feat[1], cb, 100, 100, 10000, 40000);
    conv3x3_small<<<dim3(53, 4, 2), 256>>>(feat[2], feat[3], feat[4], cb);

    // heads over all levels
    heads_kernel<<<dim3((HWT + 127) / 128, 2), 128>>>(lw, lb, dw, db);

    // top-K (all levels/batches in single launches)
    topk_hist<<<dim3(118, 10), 1024>>>();
    topk_thresh<<<10, 1024>>>();
    topk_gather<<<dim3(118, 10), 1024>>>();
    topk_final<<<10, 1024, 65536>>>(anc[0], anc[1], anc[2], anc[3], anc[4]);

    sort_kernel<<<2, 1024, 65536>>>();
    dim3 mg(CBK, CBK, 2);
    nms_mask_kernel<<<mg, 64>>>();
    nms_reduce_kernel<<<2, 32>>>();
    emit_kernel<<<dim3(4, 2), 256>>>((float*)d_out);
}

// round 17
// speedup vs baseline: 1.0852x; 1.0852x over previous
#include <cuda_runtime.h>
#include <math.h>

#define M_TOT 4507
#define CBK   71
#define POSTK 1000
#define HWT   53294      // 40000+10000+2500+625+169
#define NTOT  159882     // HWT*3
#define NSTG  4

__device__ float g_wT[2304 * 256];
__device__ float g_h[2 * 256 * HWT];
__device__ float g_scores[2 * NTOT];
__device__ float g_deltas[2 * NTOT * 4];
__device__ float g_cboxes[2 * M_TOT * 4];
__device__ float g_cscores[2 * M_TOT];
__device__ float g_sboxes[2 * M_TOT * 4];
__device__ unsigned long long g_mask[2 * M_TOT * CBK];
__device__ int g_keeplist[2 * M_TOT];
__device__ int g_kcount[2];
__device__ unsigned g_hist16[10 * 65536];
__device__ unsigned long long g_cand[10 * 8192];
__device__ unsigned g_candcnt[10];
__device__ unsigned g_thrbin[10];

__device__ __forceinline__ unsigned ordf(float f) {
    unsigned u = __float_as_uint(f);
    return u ^ (((int)u < 0) ? 0xffffffffu : 0x80000000u);
}

// ---- transpose conv weights: cw[co][k] -> wT[k*256+co], k = ci*9+o (KCRS order)
__global__ void wtrans_kernel(const float* __restrict__ cw) {
    int idx = blockIdx.x * 256 + threadIdx.x;
    if (idx < 589824) {
        int k = idx >> 8, co = idx & 255;
        g_wT[idx] = cw[co * 2304 + k];
    }
}

// ---- clear per-(level,batch) histograms + counters ----
__global__ void clear_hist(int part) {
    int i = part * 327680 + blockIdx.x * 1024 + threadIdx.x;
    if (i < 655360) g_hist16[i] = 0u;
    if (part == 0 && i < 10) g_candcnt[i] = 0u;
}

// ---- big conv (P2/P3): cp.async 4-stage pipeline, 128 couts x 64 px,
// ---- 8 couts/thread, cout-pair f32x2 accumulation, 2 CTAs/SM.
// ---- Exact KCRS k-order chain per scalar output (numerics-critical).
__global__ void __launch_bounds__(256, 2) conv3x3_big(
    const float* __restrict__ x, const float* __restrict__ bias,
    int H, int W, int HW, int lof)
{
    constexpr int CPT = 8;
    constexpr int CO = 128;
    constexpr int NP = 4;
    extern __shared__ float smem[];
    float* As = smem;                       // [NSTG][16][CO]
    float* Bs = smem + NSTG * 16 * CO;      // [NSTG][16][64]
    unsigned sb = (unsigned)__cvta_generic_to_shared(smem);
    const unsigned bOff = NSTG * 16 * CO * 4;

    const int tid = threadIdx.x;
    const int tx = tid & 15, ty = tid >> 4;
    const int nb = blockIdx.x << 6;
    const int cb = blockIdx.y * CO;
    const int b  = blockIdx.z;

    int py[4], px[4]; bool pin[4];
#pragma unroll
    for (int e = 0; e < 4; ++e) {
        int ng = nb + (tx << 2) + e;
        pin[e] = ng < HW;
        int ngc = pin[e] ? ng : 0;
        py[e] = ngc / W;
        px[e] = ngc - py[e] * W;
    }
    const float* xb = x + (size_t)b * 256 * HW;

    unsigned long long acc[NP][4];
#pragma unroll
    for (int cp = 0; cp < NP; ++cp)
#pragma unroll
        for (int e = 0; e < 4; ++e) acc[cp][e] = 0ull;

    // stage issue: A (2x16B cp.async.cg), B (4x4B cp.async.ca with zfill)
    auto issue = [&](int kt, int s) {
        const int k  = (kt << 4) + ty;
        const int ci = k / 9;
        const int o  = k - ci * 9;
        const int ot = o / 3;
        const int dy = ot - 1;
        const int dx = o - ot * 3 - 1;
        const float* wp = &g_wT[(k << 8) + cb + tx * CPT];
        unsigned ad = sb + (((s * 16 + ty) * CO + tx * CPT) << 2);
        asm volatile("cp.async.cg.shared.global [%0], [%1], 16;" :: "r"(ad), "l"(wp));
        asm volatile("cp.async.cg.shared.global [%0], [%1], 16;" :: "r"(ad + 16), "l"(wp + 4));
        const float* xc = xb + (size_t)ci * HW;
        unsigned bd = sb + bOff + (((s * 16 + ty) * 64 + (tx << 2)) << 2);
#pragma unroll
        for (int e = 0; e < 4; ++e) {
            int hh = py[e] + dy, ww = px[e] + dx;
            bool ok = pin[e] && (unsigned)hh < (unsigned)H && (unsigned)ww < (unsigned)W;
            const float* gp = ok ? (xc + hh * W + ww) : xc;
            unsigned ssz = ok ? 4u : 0u;
            asm volatile("cp.async.ca.shared.global [%0], [%1], 4, %2;"
                         :: "r"(bd + (e << 2)), "l"(gp), "r"(ssz));
        }
    };

#pragma unroll
    for (int s = 0; s < NSTG - 1; ++s) {
        issue(s, s);
        asm volatile("cp.async.commit_group;" ::: "memory");
    }

    for (int kt = 0; kt < 144; ++kt) {
        asm volatile("cp.async.wait_group %0;" :: "n"(NSTG - 2) : "memory");
        __syncthreads();
        if (kt + NSTG - 1 < 144)
            issue(kt + NSTG - 1, (kt + NSTG - 1) & (NSTG - 1));
        asm volatile("cp.async.commit_group;" ::: "memory");
        const int cur = kt & (NSTG - 1);
#pragma unroll
        for (int kk = 0; kk < 16; ++kk) {
            const float* arow = &As[(cur * 16 + kk) * CO + ty * CPT];
            ulonglong2 a01 = *(const ulonglong2*)arow;
            ulonglong2 a23 = *(const ulonglong2*)(arow + 4);
            unsigned long long A2[NP] = {a01.x, a01.y, a23.x, a23.y};
            float4 bq = *(const float4*)&Bs[(cur * 16 + kk) * 64 + (tx << 2)];
            unsigned long long B2[4];
            asm("mov.b64 %0, {%1,%1};" : "=l"(B2[0]) : "f"(bq.x));
            asm("mov.b64 %0, {%1,%1};" : "=l"(B2[1]) : "f"(bq.y));
            asm("mov.b64 %0, {%1,%1};" : "=l"(B2[2]) : "f"(bq.z));
            asm("mov.b64 %0, {%1,%1};" : "=l"(B2[3]) : "f"(bq.w));
#pragma unroll
            for (int cp = 0; cp < NP; ++cp)
#pragma unroll
                for (int e = 0; e < 4; ++e)
                    asm("fma.rn.f32x2 %0, %1, %2, %0;" : "+l"(acc[cp][e]) : "l"(A2[cp]), "l"(B2[e]));
        }
    }
#pragma unroll
    for (int cp = 0; cp < NP; ++cp) {
        int co0 = cb + ty * CPT + (cp << 1);
        float bb0 = bias[co0], bb1 = bias[co0 + 1];
        float* op0 = g_h + ((size_t)b * 256 + co0) * HWT + lof;
        float* op1 = op0 + HWT;
#pragma unroll
        for (int e = 0; e < 4; ++e) {
            int ng = nb + (tx << 2) + e;
            if (ng < HW) {
                unsigned u0, u1;
                asm("mov.b64 {%0,%1}, %2;" : "=r"(u0), "=r"(u1) : "l"(acc[cp][e]));
                float t0 = __uint_as_float(u0) + bb0;
                float t1 = __uint_as_float(u1) + bb1;
                op0[ng] = t0 > 0.f ? t0 : 0.f;
                op1[ng] = t1 > 0.f ? t1 : 0.f;
            }
        }
    }
}

// ---- fused small-level conv (P4,P5,P6) in ONE launch (R15 proven) ----
__global__ void __launch_bounds__(256, 2) conv3x3_small(
    const float* __restrict__ x4, const float* __restrict__ x5,
    const float* __restrict__ x6, const float* __restrict__ bias)
{
    __shared__ float As[2][16][64];
    __shared__ float Bs[2][16][64];
    const int bx = blockIdx.x;
    int li, base;
    if (bx < 40) { li = 0; base = 0; }
    else if (bx < 50) { li = 1; base = 40; }
    else { li = 2; base = 50; }
    const int HWa[3] = {2500, 625, 169};
    const int Wa[3]  = {50, 25, 13};
    const int lofa[3] = {50000, 52500, 53125};
    const int HW = HWa[li], W = Wa[li], lof = lofa[li];
    const float* x = (li == 0) ? x4 : (li == 1) ? x5 : x6;

    const int tid = threadIdx.x;
    const int tx = tid & 15, ty = tid >> 4;
    const int nb = (bx - base) << 6;
    const int cb = blockIdx.y << 6;
    const int b  = blockIdx.z;

    int py[4], px[4]; bool pin[4];
#pragma unroll
    for (int e = 0; e < 4; ++e) {
        int ng = nb + (tx << 2) + e;
        pin[e] = ng < HW;
        int ngc = pin[e] ? ng : 0;
        py[e] = ngc / W;
        px[e] = ngc - py[e] * W;
    }
    const float* xb = x + (size_t)b * 256 * HW;

    unsigned long long acc[2][4];
#pragma unroll
    for (int cp = 0; cp < 2; ++cp)
#pragma unroll
        for (int e = 0; e < 4; ++e) acc[cp][e] = 0ull;

    float4 av; float bv[4];
    {
        const int k  = ty;
        const int ci = k / 9;
        const int o  = k - ci * 9;
        const int ot = o / 3;
        const int dy = ot - 1;
        const int dx = o - ot * 3 - 1;
        av = *(const float4*)&g_wT[(k << 8) + cb + (tx << 2)];
        const float* xc = xb + (size_t)ci * HW;
#pragma unroll
        for (int e = 0; e < 4; ++e) {
            int hh = py[e] + dy, ww = px[e] + dx;
            bool ok = pin[e] && (unsigned)hh < (unsigned)W && (unsigned)ww < (unsigned)W;
            bv[e] = ok ? xc[hh * W + ww] : 0.f;
        }
    }

    for (int kt = 0; kt < 144; ++kt) {
        const int cur = kt & 1;
        *(float4*)&As[cur][ty][tx << 2] = av;
        *(float4*)&Bs[cur][ty][tx << 2] = make_float4(bv[0], bv[1], bv[2], bv[3]);
        __syncthreads();
        if (kt < 143) {
            const int k  = ((kt + 1) << 4) + ty;
            const int ci = k / 9;
            const int o  = k - ci * 9;
            const int ot = o / 3;
            const int dy = ot - 1;
            const int dx = o - ot * 3 - 1;
            av = *(const float4*)&g_wT[(k << 8) + cb + (tx << 2)];
            const float* xc = xb + (size_t)ci * HW;
#pragma unroll
            for (int e = 0; e < 4; ++e) {
                int hh = py[e] + dy, ww = px[e] + dx;
                bool ok = pin[e] && (unsigned)hh < (unsigned)W && (unsigned)ww < (unsigned)W;
                bv[e] = ok ? xc[hh * W + ww] : 0.f;
            }
        }
#pragma unroll
        for (int kk = 0; kk < 16; ++kk) {
            ulonglong2 aq = *(const ulonglong2*)&As[cur][kk][ty << 2];
            unsigned long long A2[2] = {aq.x, aq.y};
            float4 bq = *(const float4*)&Bs[cur][kk][tx << 2];
            unsigned long long B2[4];
            asm("mov.b64 %0, {%1,%1};" : "=l"(B2[0]) : "f"(bq.x));
            asm("mov.b64 %0, {%1,%1};" : "=l"(B2[1]) : "f"(bq.y));
            asm("mov.b64 %0, {%1,%1};" : "=l"(B2[2]) : "f"(bq.z));
            asm("mov.b64 %0, {%1,%1};" : "=l"(B2[3]) : "f"(bq.w));
#pragma unroll
            for (int cp = 0; cp < 2; ++cp)
#pragma unroll
                for (int e = 0; e < 4; ++e)
                    asm("fma.rn.f32x2 %0, %1, %2, %0;" : "+l"(acc[cp][e]) : "l"(A2[cp]), "l"(B2[e]));
        }
    }
#pragma unroll
    for (int cp = 0; cp < 2; ++cp) {
        int co0 = cb + (ty << 2) + (cp << 1);
        float bb0 = bias[co0], bb1 = bias[co0 + 1];
        float* op0 = g_h + ((size_t)b * 256 + co0) * HWT + lof;
        float* op1 = op0 + HWT;
#pragma unroll
        for (int e = 0; e < 4; ++e) {
            int ng = nb + (tx << 2) + e;
            if (ng < HW) {
                unsigned u0, u1;
                asm("mov.b64 {%0,%1}, %2;" : "=r"(u0), "=r"(u1) : "l"(acc[cp][e]));
                float t0 = __uint_as_float(u0) + bb0;
                float t1 = __uint_as_float(u1) + bb1;
                op0[ng] = t0 > 0.f ? t0 : 0.f;
                op1[ng] = t1 > 0.f ? t1 : 0.f;
            }
        }
    }
}

// ---- fused 1x1 heads over ALL levels in one launch ----
__global__ void heads_kernel(const float* __restrict__ lw, const float* __restrict__ lb,
                             const float* __restrict__ dw, const float* __restrict__ db)
{
    __shared__ float ws[15 * 256];
    __shared__ float wb[15];
    const int tid = threadIdx.x;
    for (int i = tid; i < 768;  i += 128) ws[i] = lw[i];
    for (int i = tid; i < 3072; i += 128) ws[768 + i] = dw[i];
    if (tid < 3) wb[tid] = lb[tid];
    else if (tid < 15) wb[tid] = db[tid - 3];
    __syncthreads();
    const int b = blockIdx.y;
    const int p = blockIdx.x * 128 + tid;
    if (p >= HWT) return;
    const float* hb = g_h + (size_t)b * 256 * HWT + p;
    float acc[15];
#pragma unroll
    for (int o = 0; o < 15; ++o) acc[o] = 0.f;
    for (int c = 0; c < 256; ++c) {
        float v = hb[(size_t)c * HWT];
#pragma unroll
        for (int o = 0; o < 15; ++o) acc[o] = __fmaf_rn(ws[(o << 8) + c], v, acc[o]);
    }
    size_t base = (size_t)b * NTOT + (size_t)p * 3;
#pragma unroll
    for (int a = 0; a < 3; ++a) g_scores[base + a] = acc[a] + wb[a];
#pragma unroll
    for (int a = 0; a < 3; ++a)
#pragma unroll
        for (int j = 0; j < 4; ++j)
            g_deltas[(base + a) * 4 + j] = acc[3 + (a << 2) + j] + wb[3 + (a << 2) + j];
}

__constant__ int c_Ns[5]    = {120000, 30000, 7500, 1875, 507};
__constant__ int c_soff[5]  = {0, 120000, 150000, 157500, 159375};
__constant__ int c_Ks[5]    = {1000, 1000, 1000, 1000, 507};
__constant__ int c_offs[5]  = {0, 1000, 2000, 3000, 4000};

// ==== parallel exact top-K, all (level,batch) in single launches ====
__global__ void topk_hist() {
    int lb = blockIdx.y; int lvl = lb >> 1, b = lb & 1;
    int N = c_Ns[lvl];
    unsigned* hist = g_hist16 + lb * 65536;
    const float* sc = g_scores + (size_t)b * NTOT + c_soff[lvl];
    for (int i = blockIdx.x * 1024 + threadIdx.x; i < N; i += gridDim.x * 1024)
        atomicAdd(&hist[ordf(sc[i]) >> 16], 1u);
}

__global__ void topk_thresh() {
    int lb = blockIdx.x;
    int K = c_Ks[lb >> 1];
    int tid = threadIdx.x;
    __shared__ unsigned csum[1024];
    const unsigned* hist = g_hist16 + lb * 65536;
    unsigned s = 0;
    for (int j = 0; j < 64; ++j) s += hist[tid * 64 + j];
    csum[tid] = s;
    __syncthreads();
    if (tid == 0) {
        unsigned acc = 0; int c = 0;
        for (c = 1023; c >= 0; --c) {
            if (acc + csum[c] >= (unsigned)K) break;
            acc += csum[c];
        }
        unsigned thr = 0;
        for (int j = 63; j >= 0; --j) {
            unsigned h = hist[c * 64 + j];
            if (acc + h >= (unsigned)K) { thr = c * 64 + j; break; }
            acc += h;
        }
        g_thrbin[lb] = thr;
    }
}

__global__ void topk_gather() {
    int lb = blockIdx.y; int lvl = lb >> 1, b = lb & 1;
    int N = c_Ns[lvl];
    unsigned thr = g_thrbin[lb];
    const float* sc = g_scores + (size_t)b * NTOT + c_soff[lvl];
    for (int i = blockIdx.x * 1024 + threadIdx.x; i < N; i += gridDim.x * 1024) {
        unsigned o = ordf(sc[i]);
        if ((o >> 16) >= thr) {
            unsigned p = atomicAdd(&g_candcnt[lb], 1u);
            if (p < 8192)
                g_cand[lb * 8192 + p] = (((unsigned long long)o) << 32) | (unsigned)(~i);
        }
    }
}

__global__ void topk_final(const float* __restrict__ a0, const float* __restrict__ a1,
                           const float* __restrict__ a2, const float* __restrict__ a3,
                           const float* __restrict__ a4) {
    extern __shared__ unsigned long long sk2[];
    int lb = blockIdx.x; int lvl = lb >> 1, b = lb & 1;
    int tid = threadIdx.x;
    int K = c_Ks[lvl];
    const float* ancs[5] = {a0, a1, a2, a3, a4};
    const float* anchors = ancs[lvl];
    unsigned cnt = min(g_candcnt[lb], 8192u);
    int SZ = (cnt <= 2048u) ? 2048 : 8192;
    for (int i = tid; i < SZ; i += 1024)
        sk2[i] = (i < (int)cnt) ? g_cand[lb * 8192 + i] : 0ull;
    __syncthreads();
    for (unsigned k = 2; k <= (unsigned)SZ; k <<= 1) {
        for (unsigned j = k >> 1; j; j >>= 1) {
            for (unsigned e = tid; e < (unsigned)SZ; e += 1024) {
                unsigned ixj = e ^ j;
                if (ixj > e) {
                    unsigned long long a = sk2[e], c = sk2[ixj];
                    bool up = ((e & k) == 0);
                    if ((a < c) == up) { sk2[e] = c; sk2[ixj] = a; }  // descending
                }
            }
            __syncthreads();
        }
    }
    if (tid < K) {
        unsigned long long key = sk2[tid];
        unsigned idx = ~(unsigned)(key & 0xffffffffull);
        const float* sc = g_scores + (size_t)b * NTOT + c_soff[lvl];
        float s = sc[idx];
        const float* dl = g_deltas + ((size_t)b * NTOT + c_soff[lvl] + idx) * 4;
        float d0 = dl[0], d1 = dl[1], d2 = dl[2], d3 = dl[3];
        const float* an = anchors + (size_t)idx * 4;
        float aa0 = an[0], aa1 = an[1], aa2 = an[2], aa3 = an[3];
        float wa = __fsub_rn(aa2, aa0), ha = __fsub_rn(aa3, aa1);
        float xa = __fadd_rn(aa0, __fmul_rn(0.5f, wa));
        float ya = __fadd_rn(aa1, __fmul_rn(0.5f, ha));
        float cx = __fadd_rn(__fmul_rn(d0, wa), xa);
        float cy = __fadd_rn(__fmul_rn(d1, ha), ya);
        float w  = __fmul_rn(wa, expf(d2));
        float h  = __fmul_rn(ha, expf(d3));
        float x0 = __fsub_rn(cx, __fmul_rn(0.5f, w));
        float y0 = __fsub_rn(cy, __fmul_rn(0.5f, h));
        float x1 = __fadd_rn(cx, __fmul_rn(0.5f, w));
        float y1 = __fadd_rn(cy, __fmul_rn(0.5f, h));
        x0 = fminf(fmaxf(x0, 0.f), 800.f); y0 = fminf(fmaxf(y0, 0.f), 800.f);
        x1 = fminf(fmaxf(x1, 0.f), 800.f); y1 = fminf(fmaxf(y1, 0.f), 800.f);
        bool valid = (x1 > x0) && (y1 > y0);
        int ci = b * M_TOT + c_offs[lvl] + tid;
        g_cboxes[ci * 4 + 0] = x0; g_cboxes[ci * 4 + 1] = y0;
        g_cboxes[ci * 4 + 2] = x1; g_cboxes[ci * 4 + 3] = y1;
        g_cscores[ci] = valid ? s : -1000000000.0f;
    }
}

// ---- global stable sort by descending score (bitonic over 8192) + gather ----
__global__ void sort_kernel() {
    extern __shared__ unsigned long long sk[];
    int b = blockIdx.x, tid = threadIdx.x;
    for (int i = tid; i < 8192; i += 1024) {
        unsigned long long k = 0xFFFFFFFFFFFFFFFFull;
        if (i < M_TOT) {
            float s = g_cscores[b * M_TOT + i];
            k = (((unsigned long long)(~ordf(s))) << 32) | (unsigned)i;
        }
        sk[i] = k;
    }
    __syncthreads();
    for (unsigned kk = 2; kk <= 8192; kk <<= 1) {
        for (unsigned j = kk >> 1; j; j >>= 1) {
            for (unsigned e = tid; e < 8192; e += 1024) {
                unsigned ixj = e ^ j;
                if (ixj > e) {
                    unsigned long long a = sk[e], c = sk[ixj];
                    if (((e & kk) == 0) ? (a > c) : (a < c)) { sk[e] = c; sk[ixj] = a; }
                }
            }
            __syncthreads();
        }
    }
    for (int i = tid; i < M_TOT; i += 1024) {
        unsigned idx = (unsigned)(sk[i] & 0xffffffffull);
        float4 bx = *(float4*)&g_cboxes[(b * M_TOT + idx) * 4];
        *(float4*)&g_sboxes[(b * M_TOT + i) * 4] = bx;
    }
}

// ---- NMS suppression mask (64-bit blocks) ----
__global__ void nms_mask_kernel() {
    int b = blockIdx.z;
    int rb = blockIdx.x, cbi = blockIdx.y;
    __shared__ float4 cbox[64];
    int t = threadIdx.x;
    int col0 = cbi * 64;
    if (col0 + t < M_TOT) cbox[t] = *(float4*)&g_sboxes[(b * M_TOT + col0 + t) * 4];
    else cbox[t] = make_float4(0, 0, 0, 0);
    __syncthreads();
    int row = rb * 64 + t;
    if (row >= M_TOT) return;
    float4 rbx = *(float4*)&g_sboxes[(b * M_TOT + row) * 4];
    float rarea = __fmul_rn(__fsub_rn(rbx.z, rbx.x), __fsub_rn(rbx.w, rbx.y));
    unsigned long long bits = 0;
    int cmax = min(64, M_TOT - col0);
    for (int c = 0; c < cmax; ++c) {
        int col = col0 + c;
        if (col <= row) continue;
        float4 cb = cbox[c];
        float carea = __fmul_rn(__fsub_rn(cb.z, cb.x), __fsub_rn(cb.w, cb.y));
        float lx = fmaxf(rbx.x, cb.x), ly = fmaxf(rbx.y, cb.y);
        float rx = fminf(rbx.z, cb.z), ry = fminf(rbx.w, cb.w);
        float w = fmaxf(__fsub_rn(rx, lx), 0.f), h = fmaxf(__fsub_rn(ry, ly), 0.f);
        float inter = __fmul_rn(w, h);
        float den = __fadd_rn(__fsub_rn(__fadd_rn(rarea, carea), inter), 1e-9f);
        float iou = __fdiv_rn(inter, den);
        if (iou > 0.7f) bits |= 1ull << c;
    }
    g_mask[((size_t)b * M_TOT + row) * CBK + cbi] = bits;
}

// ---- sequential NMS reduce: one warp per batch, smem double-buffered chunks ----
#define NCHUNK 16
__global__ void nms_reduce_kernel() {
    __shared__ unsigned long long buf[2][NCHUNK * CBK];
    int b = blockIdx.x;
    int lane = threadIdx.x;
    const unsigned long long* mrow = g_mask + (size_t)b * M_TOT * CBK;
    unsigned long long rm0 = 0, rm1 = 0, rm2 = 0;
    int cnt = 0;
    const int nchunks = (M_TOT + NCHUNK - 1) / NCHUNK;
    for (int i = lane; i < NCHUNK * CBK; i += 32)
        buf[0][i] = mrow[i];
    __syncwarp();
    for (int c = 0; c < nchunks; ++c) {
        int cur = c & 1, nxt = cur ^ 1;
        if (c + 1 < nchunks) {
            size_t base = (size_t)(c + 1) * NCHUNK * CBK;
            for (int i = lane; i < NCHUNK * CBK; i += 32) {
                int rr = (c + 1) * NCHUNK + i / CBK;
                buf[nxt][i] = (rr < M_TOT) ? mrow[base + i] : 0ull;
            }
        }
        int rmax = min(NCHUNK, M_TOT - c * NCHUNK);
        for (int j = 0; j < rmax; ++j) {
            int r = c * NCHUNK + j;
            int wq = r >> 6; int slot = wq >> 5; int src = wq & 31;
            unsigned long long rv = (slot == 0) ? rm0 : ((slot == 1) ? rm1 : rm2);
            unsigned long long v = __shfl_sync(0xffffffffu, rv, src);
            bool keep = !((v >> (r & 63)) & 1ull);
            if (keep) {
                unsigned long long m0 = (lane      < CBK) ? buf[cur][j * CBK + lane]      : 0ull;
                unsigned long long m1 = (lane + 32 < CBK) ? buf[cur][j * CBK + lane + 32] : 0ull;
                unsigned long long m2 = (lane + 64 < CBK) ? buf[cur][j * CBK + lane + 64] : 0ull;
                rm0 |= m0; rm1 |= m1; rm2 |= m2;
                if (lane == 0) g_keeplist[b * M_TOT + cnt] = r;
                cnt++;
            }
        }
        __syncwarp();
    }
    if (lane == 0) g_kcount[b] = cnt;
}

// ---- emit final output ----
__global__ void emit_kernel(float* out) {
    int b = blockIdx.y;
    int j = blockIdx.x * 256 + threadIdx.x;
    if (j >= POSTK) return;
    int kc = g_kcount[b];
    float4 v = make_float4(0, 0, 0, 0);
    if (j < kc) {
        int r = g_keeplist[b * M_TOT + j];
        v = *(float4*)&g_sboxes[(b * M_TOT + r) * 4];
    }
    ((float4*)out)[b * POSTK + j] = v;
}

extern "C" void kernel_launch(void* const* d_in, const int* in_sizes, int n_in,
                              void* d_out, int out_size) {
    const float *feat[5] = {0}, *anc[5] = {0};
    const float *cw = 0, *cb = 0, *lw = 0, *lb = 0, *dw = 0, *db = 0;
    for (int i = 0; i < n_in; ++i) {
        const float* p = (const float*)d_in[i];
        switch (in_sizes[i]) {
            case 20480000: feat[0] = p; break;
            case 5120000:  feat[1] = p; break;
            case 1280000:  feat[2] = p; break;
            case 320000:   feat[3] = p; break;
            case 86528:    feat[4] = p; break;
            case 480000:   anc[0] = p; break;
            case 120000:   anc[1] = p; break;
            case 30000:    anc[2] = p; break;
            case 7500:     anc[3] = p; break;
            case 2028:     anc[4] = p; break;
            case 589824:   cw = p; break;
            case 256:      cb = p; break;
            case 768:      lw = p; break;
            case 3:        lb = p; break;
            case 3072:     dw = p; break;
            case 12:       db = p; break;
        }
    }

    const int convSmem = NSTG * 16 * (128 + 64) * 4;   // 49152 B
    cudaFuncSetAttribute(conv3x3_big, cudaFuncAttributeMaxDynamicSharedMemorySize, convSmem);
    cudaFuncSetAttribute(topk_final, cudaFuncAttributeMaxDynamicSharedMemorySize, 65536);
    cudaFuncSetAttribute(sort_kernel, cudaFuncAttributeMaxDynamicSharedMemorySize, 65536);

    // launches 1-3 (slot #4 = P2 conv for ncu)
    wtrans_kernel<<<2304, 256>>>(cw);
    clear_hist<<<320, 1024>>>(0);
    clear_hist<<<320, 1024>>>(1);

    // convs
    conv3x3_big<<<dim3(625, 2, 2), 256, convSmem>>>(feat[0], cb, 200, 200, 40000, 0);
    conv3x3_big<<<dim3(157, 2, 2), 256, convSmem>>>(feat[1], cb, 100, 100, 10000, 40000);
    conv3x3_small<<<dim3(53, 4, 2), 256>>>(feat[2], feat[3], feat[4], cb);

    // heads over all levels
    heads_kernel<<<dim3((HWT + 127) / 128, 2), 128>>>(lw, lb, dw, db);

    // top-K (all levels/batches in single launches)
    topk_hist<<<dim3(118, 10), 1024>>>();
    topk_thresh<<<10, 1024>>>();
    topk_gather<<<dim3(118, 10), 1024>>>();
    topk_final<<<10, 1024, 65536>>>(anc[0], anc[1], anc[2], anc[3], anc[4]);

    sort_kernel<<<2, 1024, 65536>>>();
    dim3 mg(CBK, CBK, 2);
    nms_mask_kernel<<<mg, 64>>>();
    nms_reduce_kernel<<<2, 32>>>();
    emit_kernel<<<dim3(4, 2), 256>>>((float*)d_out);
}